// round 2
// baseline (speedup 1.0000x reference)
#include <cuda_runtime.h>
#include <math.h>

typedef unsigned long long ull;

// ---- packed f32x2 helpers (sm_103a FFMA2 path; ptxas won't auto-fuse) ----
__device__ __forceinline__ ull f2mul(ull a, ull b){
    ull d; asm("mul.rn.f32x2 %0,%1,%2;" : "=l"(d) : "l"(a), "l"(b)); return d;
}
__device__ __forceinline__ ull f2fma(ull a, ull b, ull c){
    ull d; asm("fma.rn.f32x2 %0,%1,%2,%3;" : "=l"(d) : "l"(a), "l"(b), "l"(c)); return d;
}
__device__ __forceinline__ ull f2pack(float a){
    ull d; unsigned r = __float_as_uint(a);
    asm("mov.b64 %0,{%1,%1};" : "=l"(d) : "r"(r)); return d;
}
__device__ __forceinline__ ull f2pack2(float a, float b){
    ull d;
    asm("mov.b64 %0,{%1,%2};" : "=l"(d) : "r"(__float_as_uint(a)), "r"(__float_as_uint(b)));
    return d;
}
__device__ __forceinline__ float2 f2unpack(ull a){
    unsigned lo, hi;
    asm("mov.b64 {%0,%1},%2;" : "=r"(lo), "=r"(hi) : "l"(a));
    return make_float2(__uint_as_float(lo), __uint_as_float(hi));
}

#define STRIDE 68   // staged row stride in floats (272B, 16B-aligned, conflict-free)

__global__ __launch_bounds__(128, 3)
void esh_kernel(const float* __restrict__ x0,
                const float* __restrict__ u0,
                const float* __restrict__ prec,
                const float* __restrict__ eps_p,
                float* __restrict__ out,
                int B, int n_steps)
{
    __shared__ __align__(16) ull   sh_prec[32];
    __shared__ __align__(16) float stage[4][32*STRIDE];

    const int tid  = threadIdx.x;
    const int lane = tid & 31;
    const int w    = tid >> 5;
    const int row  = blockIdx.x*128 + tid;
    const int wrow = blockIdx.x*128 + (w<<5);      // warp row base

    if (tid < 32) sh_prec[tid] = f2pack2(prec[2*tid], prec[2*tid+1]);
    __syncthreads();

    const float eps  = *eps_p;
    const float ed   = eps * (0.5f/64.0f);         // e/d  with e = eps/2, d = 64
    const ull   epsP = f2pack(eps);

    // ---- load state: 64 floats x, 64 floats u per thread (packed pairs) ----
    ull xr[32], ur[32];
    {
        const ulonglong2* xi = (const ulonglong2*)(x0) + (size_t)row*16;
        const ulonglong2* ui = (const ulonglong2*)(u0) + (size_t)row*16;
        #pragma unroll
        for (int j=0;j<16;j++){
            ulonglong2 v = xi[j]; xr[2*j]=v.x; xr[2*j+1]=v.y;
            ulonglong2 t = ui[j]; ur[2*j]=t.x; ur[2*j+1]=t.y;
        }
    }
    float r = 0.0f;

    const size_t BD  = (size_t)B*64;
    const size_t blk = (size_t)(n_steps+1)*BD;
    float* px = out +           (size_t)wrow*64;   // traj_x warp base, step 0
    float* pu = out +   blk +   (size_t)wrow*64;   // traj_u
    float* pr = out + 2*blk +   (size_t)row;       // traj_r (per-row scalar)
    const ulonglong2* sp2 = (const ulonglong2*)sh_prec;
    float* mystage = &stage[w][0];

    // Stage a 32x256B warp tile in smem, then write fully-coalesced STG.128
#define STORE_ARR(ARR, GP) do {                                              \
        _Pragma("unroll")                                                    \
        for (int j=0;j<16;j++)                                               \
            *(ulonglong2*)&mystage[lane*STRIDE + j*4] =                      \
                make_ulonglong2((ARR)[2*j], (ARR)[2*j+1]);                   \
        __syncwarp();                                                        \
        _Pragma("unroll")                                                    \
        for (int k=0;k<16;k++){                                              \
            int c = k*32 + lane;                                             \
            ulonglong2 v = *(const ulonglong2*)                              \
                &mystage[(c>>4)*STRIDE + (c&15)*4];                          \
            *(ulonglong2*)((GP) + (size_t)c*4) = v;                          \
        }                                                                    \
        __syncwarp();                                                        \
    } while(0)

#define HALF_STEP() do {                                                     \
        ull gg0=0,gg1=0,ugA=0,ugB=0;                                         \
        _Pragma("unroll")                                                    \
        for (int j=0;j<16;j++){                                              \
            ulonglong2 p = sp2[j];                                           \
            ull g0 = f2mul(p.x, xr[2*j]);                                    \
            ull g1 = f2mul(p.y, xr[2*j+1]);                                  \
            gg0 = f2fma(g0,g0,gg0);      gg1 = f2fma(g1,g1,gg1);             \
            ugA = f2fma(ur[2*j],g0,ugA); ugB = f2fma(ur[2*j+1],g1,ugB);      \
        }                                                                    \
        float2 q0=f2unpack(gg0), q1=f2unpack(gg1);                           \
        float gg = (q0.x+q0.y)+(q1.x+q1.y);                                  \
        float2 q2=f2unpack(ugA), q3=f2unpack(ugB);                           \
        float ug = (q2.x+q2.y)+(q3.x+q3.y);                                  \
        float gn0   = fmaxf(sqrtf(gg), 1e-10f);                              \
        float gnorm = fminf(gn0, 10.0f);                                     \
        float invg  = 1.0f/gn0;                                              \
        float ude   = -ug*invg;                                              \
        float t     = expf(-ed*gnorm);                                       \
        float Bc    = 2.0f*t;                                                \
        float A2    = (ude-1.0f)*(t*t);                                      \
        float A     = 1.0f + ude + A2;                                       \
        bool  cond  = ude > -0.999f;                                         \
        float c1    = cond ? invg*fmaf(Bc,ude,-A) : invg;                    \
        float c2    = cond ? Bc : 0.0f;                                      \
        float Z     = 1.0f + ude - A2;                                       \
        float dr    = cond ? fmaf(ed,gnorm, logf(0.5f*fmaxf(Z,1e-10f)))      \
                           : -ed*gnorm;                                      \
        r += dr;                                                             \
        ull c1p=f2pack(c1), c2p=f2pack(c2);                                  \
        ull n0=0, n1=0;                                                      \
        _Pragma("unroll")                                                    \
        for (int j=0;j<16;j++){                                              \
            ulonglong2 p = sp2[j];                                           \
            ull g0 = f2mul(p.x, xr[2*j]);                                    \
            ull g1 = f2mul(p.y, xr[2*j+1]);                                  \
            ull t0 = f2fma(c1p, g0, f2mul(c2p, ur[2*j]));                    \
            ull t1 = f2fma(c1p, g1, f2mul(c2p, ur[2*j+1]));                  \
            ur[2*j]=t0; ur[2*j+1]=t1;                                        \
            n0 = f2fma(t0,t0,n0); n1 = f2fma(t1,t1,n1);                      \
        }                                                                    \
        float2 q4=f2unpack(n0), q5=f2unpack(n1);                             \
        float un2 = (q4.x+q4.y)+(q5.x+q5.y);                                 \
        float sN  = 1.0f/fmaxf(sqrtf(un2), 1e-10f);                          \
        ull  sp   = f2pack(sN);                                              \
        _Pragma("unroll")                                                    \
        for (int j=0;j<32;j++) ur[j] = f2mul(ur[j], sp);                     \
    } while(0)

    // ---- step 0 slice: x0, u0, r=0 ----
    STORE_ARR(xr, px);
    STORE_ARR(ur, pu);
    *pr = 0.0f;

    for (int s=0; s<n_steps; s++){
        HALF_STEP();                                    // first half (e = eps/2)
        #pragma unroll
        for (int j=0;j<32;j++) xr[j] = f2fma(epsP, ur[j], xr[j]);   // x += eps*u
        HALF_STEP();                                    // second half
        px += BD; pu += BD; pr += B;
        STORE_ARR(xr, px);
        STORE_ARR(ur, pu);
        *pr = r;
    }

#undef HALF_STEP
#undef STORE_ARR
}

extern "C" void kernel_launch(void* const* d_in, const int* in_sizes, int n_in,
                              void* d_out, int out_size)
{
    const float* x0   = (const float*)d_in[0];
    const float* u0   = (const float*)d_in[1];
    const float* prec = (const float*)d_in[2];
    const float* eps  = (const float*)d_in[3];
    // B from x0 element count; n_steps recovered from out_size = (n+1)*B*(2*64+1)
    int B = in_sizes[0] / 64;
    long long per_slice = (long long)B * 129;
    int n_steps = (int)((long long)out_size / per_slice) - 1;
    if (n_steps < 0) n_steps = 0;

    esh_kernel<<<B/128, 128>>>(x0, u0, prec, eps, (float*)d_out, B, n_steps);
}

// round 3
// speedup vs baseline: 1.8263x; 1.8263x over previous
#include <cuda_runtime.h>
#include <math.h>

typedef unsigned long long ull;

// ---- packed f32x2 helpers (sm_103a FFMA2 path; ptxas won't auto-fuse) ----
__device__ __forceinline__ ull f2mul(ull a, ull b){
    ull d; asm("mul.rn.f32x2 %0,%1,%2;" : "=l"(d) : "l"(a), "l"(b)); return d;
}
__device__ __forceinline__ ull f2fma(ull a, ull b, ull c){
    ull d; asm("fma.rn.f32x2 %0,%1,%2,%3;" : "=l"(d) : "l"(a), "l"(b), "l"(c)); return d;
}
__device__ __forceinline__ ull f2pack(float a){
    ull d; unsigned r = __float_as_uint(a);
    asm("mov.b64 %0,{%1,%1};" : "=l"(d) : "r"(r)); return d;
}
__device__ __forceinline__ float2 f2unpack(ull a){
    unsigned lo, hi;
    asm("mov.b64 {%0,%1},%2;" : "=r"(lo), "=r"(hi) : "l"(a));
    return make_float2(__uint_as_float(lo), __uint_as_float(hi));
}

// reduce across the 8-lane group (lanes 0-7, 8-15, ...)
__device__ __forceinline__ float red8(float v){
    v += __shfl_xor_sync(0xffffffffu, v, 1);
    v += __shfl_xor_sync(0xffffffffu, v, 2);
    v += __shfl_xor_sync(0xffffffffu, v, 4);
    return v;
}

__global__ __launch_bounds__(256)
void esh_kernel(const float* __restrict__ x0,
                const float* __restrict__ u0,
                const float* __restrict__ prec,
                const float* __restrict__ eps_p,
                float* __restrict__ out,
                int B, int n_steps)
{
    const int tid = threadIdx.x;
    const int c   = tid & 7;                       // sub-row lane (0..7)
    const int row = blockIdx.x*32 + (tid >> 3);    // 32 rows per 256-thread block

    const float eps = *eps_p;
    const float ed  = eps * (0.5f/64.0f);          // e/d, e = eps/2, d = 64
    const ull   epsP = f2pack(eps);

    // column offsets (floats): cols [c*4, c*4+4) and [32+c*4, 32+c*4+4)
    const int o0 = c*4, o1 = 32 + c*4;

    // ---- per-thread state: 8 floats x, 8 floats u, 8 floats prec (packed) ----
    ull xp[4], up[4], pp[4];
    {
        const float* xb = x0 + (size_t)row*64;
        const float* ub = u0 + (size_t)row*64;
        ulonglong2 v;
        v = *(const ulonglong2*)(xb + o0); xp[0]=v.x; xp[1]=v.y;
        v = *(const ulonglong2*)(xb + o1); xp[2]=v.x; xp[3]=v.y;
        v = *(const ulonglong2*)(ub + o0); up[0]=v.x; up[1]=v.y;
        v = *(const ulonglong2*)(ub + o1); up[2]=v.x; up[3]=v.y;
        v = *(const ulonglong2*)(prec + o0); pp[0]=v.x; pp[1]=v.y;
        v = *(const ulonglong2*)(prec + o1); pp[2]=v.x; pp[3]=v.y;
    }
    float r = 0.0f;

    const size_t BD  = (size_t)B*64;
    const size_t blk = (size_t)(n_steps+1)*BD;
    float* px = out +           (size_t)row*64;    // traj_x
    float* pu = out +   blk +   (size_t)row*64;    // traj_u
    float* pr = out + 2*blk +   (size_t)row;       // traj_r

    // perfectly coalesced direct register stores: lanes 0-7 fill one 128B line
#define STORE(ARR, GP) do {                                         \
        *(ulonglong2*)((GP) + o0) = make_ulonglong2((ARR)[0],(ARR)[1]); \
        *(ulonglong2*)((GP) + o1) = make_ulonglong2((ARR)[2],(ARR)[3]); \
    } while(0)

#define HALF_STEP() do {                                                     \
        ull gg2=0, ug2=0;                                                    \
        _Pragma("unroll")                                                    \
        for (int j=0;j<4;j++){                                               \
            ull g = f2mul(pp[j], xp[j]);                                     \
            gg2 = f2fma(g,g,gg2);                                            \
            ug2 = f2fma(up[j],g,ug2);                                        \
        }                                                                    \
        float2 qa=f2unpack(gg2), qb=f2unpack(ug2);                           \
        float gg = red8(qa.x+qa.y);                                          \
        float ug = red8(qb.x+qb.y);                                          \
        float gn0   = fmaxf(sqrtf(gg), 1e-10f);                              \
        float gnorm = fminf(gn0, 10.0f);                                     \
        float invg  = 1.0f/gn0;                                              \
        float ude   = -ug*invg;                                              \
        float t     = expf(-ed*gnorm);                                       \
        float Bc    = 2.0f*t;                                                \
        float A2    = (ude-1.0f)*(t*t);                                      \
        float A     = 1.0f + ude + A2;                                       \
        bool  cond  = ude > -0.999f;                                         \
        float c1    = cond ? invg*fmaf(Bc,ude,-A) : invg;                    \
        float c2    = cond ? Bc : 0.0f;                                      \
        float Z     = 1.0f + ude - A2;                                       \
        float dr    = cond ? fmaf(ed,gnorm, logf(0.5f*fmaxf(Z,1e-10f)))      \
                           : -ed*gnorm;                                      \
        r += dr;                                                             \
        ull c1p=f2pack(c1), c2p=f2pack(c2);                                  \
        ull n2=0;                                                            \
        _Pragma("unroll")                                                    \
        for (int j=0;j<4;j++){                                               \
            ull g  = f2mul(pp[j], xp[j]);                                    \
            ull tn = f2fma(c1p, g, f2mul(c2p, up[j]));                       \
            up[j]=tn; n2 = f2fma(tn,tn,n2);                                  \
        }                                                                    \
        float2 qn=f2unpack(n2);                                              \
        float un2 = red8(qn.x+qn.y);                                         \
        float sN  = 1.0f/fmaxf(sqrtf(un2), 1e-10f);                          \
        ull  sp   = f2pack(sN);                                              \
        _Pragma("unroll")                                                    \
        for (int j=0;j<4;j++) up[j] = f2mul(up[j], sp);                      \
    } while(0)

    // ---- step 0 slice: x0, u0, r=0 ----
    STORE(xp, px);
    STORE(up, pu);
    if (c == 0) *pr = 0.0f;

    for (int s=0; s<n_steps; s++){
        HALF_STEP();                                   // first half (e = eps/2)
        #pragma unroll
        for (int j=0;j<4;j++) xp[j] = f2fma(epsP, up[j], xp[j]);  // x += eps*u
        HALF_STEP();                                   // second half
        px += BD; pu += BD; pr += B;
        STORE(xp, px);
        STORE(up, pu);
        if (c == 0) *pr = r;
    }

#undef HALF_STEP
#undef STORE
}

extern "C" void kernel_launch(void* const* d_in, const int* in_sizes, int n_in,
                              void* d_out, int out_size)
{
    const float* x0   = (const float*)d_in[0];
    const float* u0   = (const float*)d_in[1];
    const float* prec = (const float*)d_in[2];
    const float* eps  = (const float*)d_in[3];
    int B = in_sizes[0] / 64;
    long long per_slice = (long long)B * 129;
    int n_steps = (int)((long long)out_size / per_slice) - 1;
    if (n_steps < 0) n_steps = 0;

    // 32 rows per block (256 threads, 8 threads/row)
    esh_kernel<<<B/32, 256>>>(x0, u0, prec, eps, (float*)d_out, B, n_steps);
}

// round 4
// speedup vs baseline: 2.1776x; 1.1924x over previous
#include <cuda_runtime.h>
#include <math.h>

typedef unsigned long long ull;

// ---- packed f32x2 helpers (sm_103a FFMA2 path; ptxas won't auto-fuse) ----
__device__ __forceinline__ ull f2mul(ull a, ull b){
    ull d; asm("mul.rn.f32x2 %0,%1,%2;" : "=l"(d) : "l"(a), "l"(b)); return d;
}
__device__ __forceinline__ ull f2fma(ull a, ull b, ull c){
    ull d; asm("fma.rn.f32x2 %0,%1,%2,%3;" : "=l"(d) : "l"(a), "l"(b), "l"(c)); return d;
}
__device__ __forceinline__ ull f2pack(float a){
    ull d; unsigned r = __float_as_uint(a);
    asm("mov.b64 %0,{%1,%1};" : "=l"(d) : "r"(r)); return d;
}
__device__ __forceinline__ float2 f2unpack(ull a){
    unsigned lo, hi;
    asm("mov.b64 {%0,%1},%2;" : "=r"(lo), "=r"(hi) : "l"(a));
    return make_float2(__uint_as_float(lo), __uint_as_float(hi));
}

// ---- MUFU fast paths ----
__device__ __forceinline__ float rsqf(float x){
    float y; asm("rsqrt.approx.f32 %0,%1;" : "=f"(y) : "f"(x)); return y;
}
__device__ __forceinline__ float ex2f(float x){
    float y; asm("ex2.approx.f32 %0,%1;" : "=f"(y) : "f"(x)); return y;
}
__device__ __forceinline__ float lg2f(float x){
    float y; asm("lg2.approx.f32 %0,%1;" : "=f"(y) : "f"(x)); return y;
}

// reduce across the 8-lane group (lanes 0-7, 8-15, ...)
__device__ __forceinline__ float red8(float v){
    v += __shfl_xor_sync(0xffffffffu, v, 1);
    v += __shfl_xor_sync(0xffffffffu, v, 2);
    v += __shfl_xor_sync(0xffffffffu, v, 4);
    return v;
}

#define LOG2E 1.4426950408889634f
#define LN2   0.6931471805599453f

__global__ __launch_bounds__(256)
void esh_kernel(const float* __restrict__ x0,
                const float* __restrict__ u0,
                const float* __restrict__ prec,
                const float* __restrict__ eps_p,
                float* __restrict__ out,
                int B, int n_steps)
{
    const int tid = threadIdx.x;
    const int c   = tid & 7;                       // sub-row lane (0..7)
    const int row = blockIdx.x*32 + (tid >> 3);    // 32 rows per 256-thread block

    const float eps = *eps_p;
    const float ed  = eps * (0.5f/64.0f);          // e/d, e = eps/2, d = 64
    const float k1  = -ed * LOG2E;                 // exp(-ed*g) = ex2(k1*g)

    // column offsets (floats): cols [c*4, c*4+4) and [32+c*4, 32+c*4+4)
    const int o0 = c*4, o1 = 32 + c*4;

    // ---- per-thread state: 8 floats x, 8 floats u, 8 floats prec (packed) ----
    ull xp[4], up[4], pp[4];
    {
        const float* xb = x0 + (size_t)row*64;
        const float* ub = u0 + (size_t)row*64;
        ulonglong2 v;
        v = *(const ulonglong2*)(xb + o0); xp[0]=v.x; xp[1]=v.y;
        v = *(const ulonglong2*)(xb + o1); xp[2]=v.x; xp[3]=v.y;
        v = *(const ulonglong2*)(ub + o0); up[0]=v.x; up[1]=v.y;
        v = *(const ulonglong2*)(ub + o1); up[2]=v.x; up[3]=v.y;
        v = *(const ulonglong2*)(prec + o0); pp[0]=v.x; pp[1]=v.y;
        v = *(const ulonglong2*)(prec + o1); pp[2]=v.x; pp[3]=v.y;
    }
    float r  = 0.0f;
    float us = 1.0f;                               // true u = us * up (deferred renorm)

    const size_t BD  = (size_t)B*64;
    const size_t blk = (size_t)(n_steps+1)*BD;
    float* px = out +           (size_t)row*64;    // traj_x
    float* pu = out +   blk +   (size_t)row*64;    // traj_u
    float* pr = out + 2*blk +   (size_t)row;       // traj_r

    // perfectly coalesced streaming register stores (evict-first: never re-read)
#define STORE2(A0, A1, GP) do {                                          \
        __stcs((ulonglong2*)((GP) + o0), make_ulonglong2((A0), (A1)));   \
    } while(0)

    // HALF_STEP: consumes xp (positions), up+us (scaled direction); updates up, us, r
#define HALF_STEP() do {                                                     \
        ull gr[4];                                                           \
        ull gg2=0, ug2=0;                                                    \
        _Pragma("unroll")                                                    \
        for (int j=0;j<4;j++){                                               \
            gr[j] = f2mul(pp[j], xp[j]);                                     \
            gg2 = f2fma(gr[j],gr[j],gg2);                                    \
            ug2 = f2fma(up[j],gr[j],ug2);                                    \
        }                                                                    \
        float2 qa=f2unpack(gg2), qb=f2unpack(ug2);                           \
        float gg = red8(qa.x+qa.y);                                          \
        float ug = red8(qb.x+qb.y);                                          \
        gg = fmaxf(gg, 1e-20f);                                              \
        float invg  = rsqf(gg);                                              \
        float gn0   = gg*invg;                     /* = sqrt(gg) >= 1e-10 */ \
        float gnorm = fminf(gn0, 10.0f);                                     \
        float ude   = -(ug*us)*invg;                                         \
        float t     = ex2f(k1*gnorm);                                        \
        float Bc    = 2.0f*t;                                                \
        float A2    = (ude-1.0f)*(t*t);                                      \
        float A     = 1.0f + ude + A2;                                       \
        bool  cond  = ude > -0.999f;                                         \
        float c1    = cond ? invg*fmaf(Bc,ude,-A) : invg;                    \
        float c2s   = (cond ? Bc : 0.0f) * us;                               \
        float Z     = 1.0f + ude - A2;                                       \
        float dr    = cond ? fmaf(ed,gnorm,                                  \
                           LN2*lg2f(fmaxf(0.5f*Z, 5e-11f)))                  \
                           : -ed*gnorm;                                      \
        r += dr;                                                             \
        ull c1p=f2pack(c1), c2p=f2pack(c2s);                                 \
        ull n2=0;                                                            \
        _Pragma("unroll")                                                    \
        for (int j=0;j<4;j++){                                               \
            ull tn = f2fma(c1p, gr[j], f2mul(c2p, up[j]));                   \
            up[j]=tn; n2 = f2fma(tn,tn,n2);                                  \
        }                                                                    \
        float2 qn=f2unpack(n2);                                              \
        float un2 = red8(qn.x+qn.y);                                         \
        us = rsqf(fmaxf(un2, 1e-20f));                                       \
    } while(0)

    // ---- step 0 slice: x0, u0 (already unit), r=0 ----
    STORE2(xp[0], xp[1], px);  STORE2(xp[2], xp[3], px + 32);
    STORE2(up[0], up[1], pu);  STORE2(up[2], up[3], pu + 32);
    if (c == 0) *pr = 0.0f;

    for (int s=0; s<n_steps; s++){
        HALF_STEP();                                   // first half (e = eps/2)
        {
            ull es = f2pack(eps*us);                   // fold renorm into x-update
            #pragma unroll
            for (int j=0;j<4;j++) xp[j] = f2fma(es, up[j], xp[j]);
        }
        HALF_STEP();                                   // second half
        px += BD; pu += BD; pr += B;
        STORE2(xp[0], xp[1], px);  STORE2(xp[2], xp[3], px + 32);
        {
            ull usp = f2pack(us);                      // normalized u for output
            ull n0 = f2mul(up[0], usp), n1 = f2mul(up[1], usp);
            ull n2_ = f2mul(up[2], usp), n3 = f2mul(up[3], usp);
            STORE2(n0, n1, pu);  STORE2(n2_, n3, pu + 32);
        }
        if (c == 0) *pr = r;
    }

#undef HALF_STEP
#undef STORE2
}

extern "C" void kernel_launch(void* const* d_in, const int* in_sizes, int n_in,
                              void* d_out, int out_size)
{
    const float* x0   = (const float*)d_in[0];
    const float* u0   = (const float*)d_in[1];
    const float* prec = (const float*)d_in[2];
    const float* eps  = (const float*)d_in[3];
    int B = in_sizes[0] / 64;
    long long per_slice = (long long)B * 129;
    int n_steps = (int)((long long)out_size / per_slice) - 1;
    if (n_steps < 0) n_steps = 0;

    // 32 rows per block (256 threads, 8 threads/row)
    esh_kernel<<<B/32, 256>>>(x0, u0, prec, eps, (float*)d_out, B, n_steps);
}